// round 10
// baseline (speedup 1.0000x reference)
#include <cuda_runtime.h>
#include <math.h>
#include <stdint.h>

#define BB   512
#define LL   256
#define HH   512
#define AD   128
#define CD   512
#define G4H  2048      // 4*H
#define BH   (BB*HH)   // 262144

// ---------------- device scratch ----------------
__device__ alignas(16) float g_gates[BB * G4H];     // 4 MB
__device__ alignas(16) float g_vbias[G4H];
__device__ alignas(16) float g_atth[BB * AD];
__device__ alignas(16) float g_scores[BB * LL];
__device__ alignas(16) float g_weight[BB * LL];
__device__ alignas(16) float g_attres[BB * CD];

__device__ __forceinline__ float sigf(float x) { return 1.0f / (1.0f + expf(-x)); }

__device__ __forceinline__ float tanh_ap(float x) {
    float y;
    asm("tanh.approx.f32 %0, %1;" : "=f"(y) : "f"(x));
    return y;
}

// D += A*B, m16n8k8 tf32 (raw fp32 bits -> HW truncates mantissa)
__device__ __forceinline__ void mma8(float* c, const uint32_t* a, const uint32_t* b) {
    asm volatile("mma.sync.aligned.m16n8k8.row.col.f32.tf32.tf32.f32 "
        "{%0,%1,%2,%3}, {%4,%5,%6,%7}, {%8,%9}, {%0,%1,%2,%3};"
        : "+f"(c[0]), "+f"(c[1]), "+f"(c[2]), "+f"(c[3])
        : "r"(a[0]), "r"(a[1]), "r"(a[2]), "r"(a[3]), "r"(b[0]), "r"(b[1]));
}

__device__ __forceinline__ uint32_t smaddr(const void* p) {
    return (uint32_t)__cvta_generic_to_shared(p);
}
__device__ __forceinline__ void cp16(uint32_t dst, const void* src) {
    asm volatile("cp.async.cg.shared.global [%0], [%1], 16;" :: "r"(dst), "l"(src));
}
__device__ __forceinline__ void cp_commit() { asm volatile("cp.async.commit_group;"); }
template<int N> __device__ __forceinline__ void cp_wait() {
    asm volatile("cp.async.wait_group %0;" :: "n"(N));
}

// ---------------- layer-0 bias: one warp per n, coalesced
__global__ void k_vbias(const float* __restrict__ video,
                        const float* __restrict__ w_ih0,
                        const float* __restrict__ b_ih0,
                        const float* __restrict__ b_hh0) {
    int warp = (blockIdx.x * blockDim.x + threadIdx.x) >> 5;
    int lane = threadIdx.x & 31;
    if (warp >= G4H) return;
    const float* w = w_ih0 + (size_t)warp * 1536 + 512;
    float acc = 0.0f;
    #pragma unroll
    for (int i = 0; i < 16; i++) {
        int k = i * 32 + lane;
        acc += video[k] * w[k];
    }
    #pragma unroll
    for (int o = 16; o > 0; o >>= 1)
        acc += __shfl_xor_sync(0xffffffff, acc, o);
    if (lane == 0) g_vbias[warp] = acc + b_ih0[warp] + b_hh0[warp];
}

// ================= tf32 3-pair NT GEMM (R6 design: 4 warps, 64x64, 3-stage) ======
__device__ __forceinline__ void gemm_pair64(
    const float* __restrict__ Ap, int lda,
    const float* __restrict__ Wp, int ldw,
    int m0, int n0, int tid, int lane, int wm, int wn,
    uint32_t* As, uint32_t* Bs,     // each 3 stages x 64*20
    float acc[2][4][4])
{
    int lrow = tid >> 2;               // 0..31
    int kc   = (tid & 3) * 4;          // 0,4,8,12
    const float* a0p = Ap + (size_t)(m0 + lrow) * lda + kc;
    const float* a1p = Ap + (size_t)(m0 + lrow + 32) * lda + kc;
    const float* b0p = Wp + (size_t)(n0 + lrow) * ldw + kc;
    const float* b1p = Wp + (size_t)(n0 + lrow + 32) * ldw + kc;
    uint32_t sa0 = smaddr(As + lrow * 20 + kc);
    uint32_t sa1 = smaddr(As + (lrow + 32) * 20 + kc);
    uint32_t sb0 = smaddr(Bs + lrow * 20 + kc);
    uint32_t sb1 = smaddr(Bs + (lrow + 32) * 20 + kc);
    const uint32_t SBY = 64 * 20 * 4;  // stage stride bytes

    #pragma unroll
    for (int st = 0; st < 3; st++) {
        int k0 = st * 16;
        cp16(sa0 + st * SBY, a0p + k0);
        cp16(sa1 + st * SBY, a1p + k0);
        cp16(sb0 + st * SBY, b0p + k0);
        cp16(sb1 + st * SBY, b1p + k0);
        cp_commit();
    }

    int stage = 0;
    for (int s = 0; s < 32; s++) {
        cp_wait<2>();
        __syncthreads();
        const uint32_t* Ab = As + stage * 1280;
        const uint32_t* Bb = Bs + stage * 1280;
        #pragma unroll
        for (int kk = 0; kk < 16; kk += 8) {
            uint32_t af[2][4], bf[4][2];
            int ar = wm + (lane >> 2);
            int ac = kk + (lane & 3);
            #pragma unroll
            for (int mt = 0; mt < 2; mt++) {
                int r = ar + mt * 16;
                af[mt][0] = Ab[r * 20 + ac];
                af[mt][1] = Ab[(r + 8) * 20 + ac];
                af[mt][2] = Ab[r * 20 + ac + 4];
                af[mt][3] = Ab[(r + 8) * 20 + ac + 4];
            }
            #pragma unroll
            for (int nt = 0; nt < 4; nt++) {
                int c = wn + nt * 8 + (lane >> 2);
                bf[nt][0] = Bb[c * 20 + ac];
                bf[nt][1] = Bb[c * 20 + ac + 4];
            }
            #pragma unroll
            for (int mt = 0; mt < 2; mt++)
                #pragma unroll
                for (int nt = 0; nt < 4; nt++)
                    mma8(acc[mt][nt], af[mt], bf[nt]);
        }
        __syncthreads();
        if (s < 29) {
            int k0 = (s + 3) * 16;
            cp16(sa0 + stage * SBY, a0p + k0);
            cp16(sa1 + stage * SBY, a1p + k0);
            cp16(sb0 + stage * SBY, b0p + k0);
            cp16(sb1 + stage * SBY, b1p + k0);
        }
        cp_commit();
        stage++; if (stage == 3) stage = 0;
    }
}

__global__ __launch_bounds__(128)
void k_gemm3_tf32(const float* __restrict__ A0, int lda0, const float* __restrict__ W0, int ldw0,
                  const float* __restrict__ A1, int lda1, const float* __restrict__ W1, int ldw1,
                  const float* __restrict__ A2, int lda2, const float* __restrict__ W2, int ldw2,
                  const float* __restrict__ bias0, const float* __restrict__ bias1,
                  int a0_mode, int bias_mode)
{
    __shared__ uint32_t As[3 * 64 * 20];
    __shared__ uint32_t Bs[3 * 64 * 20];
    int tid = threadIdx.x;
    int wid = tid >> 5, lane = tid & 31;
    int m0 = blockIdx.y * 64, n0 = blockIdx.x * 64;
    int wm = (wid >> 1) * 32, wn = (wid & 1) * 32;

    if (a0_mode) A0 = g_attres;

    float acc[2][4][4];
    #pragma unroll
    for (int i = 0; i < 2; i++)
        #pragma unroll
        for (int j = 0; j < 4; j++)
            #pragma unroll
            for (int k = 0; k < 4; k++) acc[i][j][k] = 0.0f;

    gemm_pair64(A0, lda0, W0, ldw0, m0, n0, tid, lane, wm, wn, As, Bs, acc);
    gemm_pair64(A1, lda1, W1, ldw1, m0, n0, tid, lane, wm, wn, As, Bs, acc);
    gemm_pair64(A2, lda2, W2, ldw2, m0, n0, tid, lane, wm, wn, As, Bs, acc);

    #pragma unroll
    for (int mt = 0; mt < 2; mt++) {
        int r = m0 + wm + mt * 16 + (lane >> 2);
        #pragma unroll
        for (int nt = 0; nt < 4; nt++) {
            int c = n0 + wn + nt * 8 + 2 * (lane & 3);
            float b0, b1;
            if (bias_mode) { b0 = g_vbias[c]; b1 = g_vbias[c + 1]; }
            else           { b0 = bias0[c] + bias1[c]; b1 = bias0[c + 1] + bias1[c + 1]; }
            g_gates[(size_t)r * G4H + c]           = acc[mt][nt][0] + b0;
            g_gates[(size_t)r * G4H + c + 1]       = acc[mt][nt][1] + b1;
            g_gates[(size_t)(r + 8) * G4H + c]     = acc[mt][nt][2] + b0;
            g_gates[(size_t)(r + 8) * G4H + c + 1] = acc[mt][nt][3] + b1;
        }
    }
}

// ---------------- LSTM activation: g_gates -> (h, c)
__global__ void k_lstm_act(const float* __restrict__ cprev,
                           float* __restrict__ hout, float* __restrict__ cout,
                           float* __restrict__ hout2) {
    int idx = blockIdx.x * blockDim.x + threadIdx.x;
    if (idx >= BH) return;
    int b = idx / HH, j = idx % HH;
    const float* g = g_gates + (size_t)b * G4H;
    float gi = g[j], gf = g[HH + j], gg = g[2 * HH + j], go = g[3 * HH + j];
    float c = sigf(gf) * cprev[idx] + sigf(gi) * tanhf(gg);
    float h = sigf(go) * tanhf(c);
    hout[idx] = h;
    cout[idx] = c;
    if (hout2) hout2[idx] = h;
}

// ---------------- att_h = h1 @ wh.T + bh  ([B,128])
__global__ void k_atth(const float* __restrict__ h1, const float* __restrict__ wh,
                       const float* __restrict__ bh) {
    __shared__ float hs[512];
    int b = blockIdx.x, t = threadIdx.x;   // 128 threads
    for (int i = t; i < 512; i += 128) hs[i] = h1[(size_t)b * 512 + i];
    __syncthreads();
    const float* w = wh + (size_t)t * 512;
    float acc = bh[t];
    #pragma unroll 8
    for (int k = 0; k < 512; k++) acc += hs[k] * w[k];
    g_atth[b * AD + t] = acc;
}

// ====== fused attention scores: 64x128 block, 8 warps (2m x 4n), 3-STAGE cp.async ======
__global__ __launch_bounds__(256)
void k_att_scores(const float* __restrict__ clip, const float* __restrict__ wc,
                  const float* __restrict__ bc, const float* __restrict__ wa,
                  const float* __restrict__ ba) {
    __shared__ uint32_t As[3 * 64 * 20];    // 15 KB
    __shared__ uint32_t Bs[3 * 128 * 20];   // 30 KB
    __shared__ float red[64 * 5];           // 1.25 KB (after in-quad shuffle)
    __shared__ float addsh[128], wash[128]; // 1 KB

    int tid = threadIdx.x;
    int wid = tid >> 5, lane = tid & 31;
    int m0 = blockIdx.x * 64;           // row within [B*L]
    int bidx = blockIdx.x >> 2;         // batch (4 blocks per batch, L=256)
    int wm = (wid >> 2) * 32;           // 0 or 32
    int wn = (wid & 3) * 32;            // 0,32,64,96

    if (tid < 128) {
        addsh[tid] = bc[tid] + g_atth[bidx * AD + tid];
        wash[tid] = wa[tid];
    }

    // loaders: A 64x16 (1 cp16/thr), B 128x16 (2 cp16/thr)
    int lrowA = tid >> 2;               // 0..63
    int kcA   = (tid & 3) * 4;
    int lrowB = tid >> 1;               // 0..127
    int kcB   = (tid & 1) * 8;
    const float* apg = clip + (size_t)(m0 + lrowA) * CD + kcA;
    const float* bpg = wc + (size_t)lrowB * CD + kcB;
    uint32_t sa = smaddr(As + lrowA * 20 + kcA);
    uint32_t sb = smaddr(Bs + lrowB * 20 + kcB);
    const uint32_t SA = 64 * 20 * 4, SB = 128 * 20 * 4;

    float acc[2][4][4];
    #pragma unroll
    for (int i = 0; i < 2; i++)
        #pragma unroll
        for (int j = 0; j < 4; j++)
            #pragma unroll
            for (int k = 0; k < 4; k++) acc[i][j][k] = 0.0f;

    #pragma unroll
    for (int st = 0; st < 3; st++) {
        int k0 = st * 16;
        cp16(sa + st * SA, apg + k0);
        cp16(sb + st * SB, bpg + k0);
        cp16(sb + st * SB + 16, bpg + k0 + 4);
        cp_commit();
    }

    int stage = 0;
    for (int s = 0; s < 32; s++) {
        cp_wait<2>();
        __syncthreads();
        const uint32_t* Ab = As + stage * 1280;
        const uint32_t* Bb = Bs + stage * 2560;
        #pragma unroll
        for (int kk = 0; kk < 16; kk += 8) {
            uint32_t af[2][4], bf[4][2];
            int ar = wm + (lane >> 2);
            int ac = kk + (lane & 3);
            #pragma unroll
            for (int mt = 0; mt < 2; mt++) {
                int r = ar + mt * 16;
                af[mt][0] = Ab[r * 20 + ac];
                af[mt][1] = Ab[(r + 8) * 20 + ac];
                af[mt][2] = Ab[r * 20 + ac + 4];
                af[mt][3] = Ab[(r + 8) * 20 + ac + 4];
            }
            #pragma unroll
            for (int nt = 0; nt < 4; nt++) {
                int c = wn + nt * 8 + (lane >> 2);
                bf[nt][0] = Bb[c * 20 + ac];
                bf[nt][1] = Bb[c * 20 + ac + 4];
            }
            #pragma unroll
            for (int mt = 0; mt < 2; mt++)
                #pragma unroll
                for (int nt = 0; nt < 4; nt++)
                    mma8(acc[mt][nt], af[mt], bf[nt]);
        }
        __syncthreads();
        if (s < 29) {
            int k0 = (s + 3) * 16;
            cp16(sa + stage * SA, apg + k0);
            cp16(sb + stage * SB, bpg + k0);
            cp16(sb + stage * SB + 16, bpg + k0 + 4);
        }
        cp_commit();
        stage++; if (stage == 3) stage = 0;
    }

    // epilogue: HW tanh + dot with wa; reduce within quad, then across n-warps
    float ps[2][2] = {{0.0f, 0.0f}, {0.0f, 0.0f}};
    #pragma unroll
    for (int mt = 0; mt < 2; mt++) {
        #pragma unroll
        for (int nt = 0; nt < 4; nt++) {
            int c = wn + nt * 8 + 2 * (lane & 3);
            float a0 = addsh[c], a1 = addsh[c + 1];
            float w0 = wash[c], w1 = wash[c + 1];
            float t0 = tanh_ap(acc[mt][nt][0] + a0);
            float t1 = tanh_ap(acc[mt][nt][1] + a1);
            float t2 = tanh_ap(acc[mt][nt][2] + a0);
            float t3 = tanh_ap(acc[mt][nt][3] + a1);
            ps[mt][0] += t0 * w0 + t1 * w1;
            ps[mt][1] += t2 * w0 + t3 * w1;
        }
    }
    // in-quad reduction (lanes lane&3 = 0..3 hold same rows, different columns)
    #pragma unroll
    for (int o = 1; o <= 2; o <<= 1) {
        ps[0][0] += __shfl_xor_sync(0xffffffff, ps[0][0], o);
        ps[0][1] += __shfl_xor_sync(0xffffffff, ps[0][1], o);
        ps[1][0] += __shfl_xor_sync(0xffffffff, ps[1][0], o);
        ps[1][1] += __shfl_xor_sync(0xffffffff, ps[1][1], o);
    }
    if ((lane & 3) == 0) {
        int wq = wid & 3;               // n-warp index 0..3
        int lq = lane >> 2;             // 0..7
        #pragma unroll
        for (int mt = 0; mt < 2; mt++) {
            int r = wm + mt * 16 + lq;
            red[r * 5 + wq] = ps[mt][0];
            red[(r + 8) * 5 + wq] = ps[mt][1];
        }
    }
    __syncthreads();
    if (tid < 64) {
        float s = ba[0] + red[tid * 5] + red[tid * 5 + 1] + red[tid * 5 + 2] + red[tid * 5 + 3];
        g_scores[m0 + tid] = s;
    }
}

// ---------------- masked softmax + renorm (per batch row, L=256)
__global__ void k_softmax(const int* __restrict__ mask) {
    __shared__ float sh[256];
    int b = blockIdx.x, t = threadIdx.x;
    float s = g_scores[b * LL + t];
    sh[t] = s;
    __syncthreads();
    for (int o = 128; o > 0; o >>= 1) {
        if (t < o) sh[t] = fmaxf(sh[t], sh[t + o]);
        __syncthreads();
    }
    float mx = sh[0];
    __syncthreads();
    float p = expf(s - mx);
    float pm = p * (float)mask[b * LL + t];
    sh[t] = pm;
    __syncthreads();
    for (int o = 128; o > 0; o >>= 1) {
        if (t < o) sh[t] += sh[t + o];
        __syncthreads();
    }
    float denom = sh[0];
    g_weight[b * LL + t] = pm / denom;
}

// ---------------- att_res[b,c] = sum_l weight[b,l]*clip[b,l,c], 2 L-halves, 256 thr
__global__ void k_attres(const float* __restrict__ clip) {
    __shared__ float w[256];
    __shared__ float part[512];
    int b = blockIdx.x, t = threadIdx.x;   // 256 threads
    w[t] = g_weight[b * LL + t];
    __syncthreads();
    int half = t >> 7, tt = t & 127;
    const float* cb = clip + (size_t)b * LL * CD + (size_t)half * 128 * CD;
    const float* wl = w + half * 128;
    float4 a = make_float4(0.0f, 0.0f, 0.0f, 0.0f);
    #pragma unroll 4
    for (int l = 0; l < 128; l++) {
        float wv = wl[l];
        float4 v = *reinterpret_cast<const float4*>(cb + (size_t)l * CD + tt * 4);
        a.x += wv * v.x; a.y += wv * v.y; a.z += wv * v.z; a.w += wv * v.w;
    }
    if (half) *reinterpret_cast<float4*>(&part[tt * 4]) = a;
    __syncthreads();
    if (!half) {
        float4 p = *reinterpret_cast<const float4*>(&part[tt * 4]);
        a.x += p.x; a.y += p.y; a.z += p.z; a.w += p.w;
        *reinterpret_cast<float4*>(&g_attres[b * CD + tt * 4]) = a;
    }
}

// ---------------- launch ----------------
extern "C" void kernel_launch(void* const* d_in, const int* in_sizes, int n_in,
                              void* d_out, int out_size) {
    const float* xt      = (const float*)d_in[0];
    const float* video   = (const float*)d_in[1];
    const float* event   = (const float*)d_in[2];
    const float* clip    = (const float*)d_in[3];
    const int*   cmask   = (const int*)d_in[4];
    const float* state_h = (const float*)d_in[5];
    const float* state_c = (const float*)d_in[6];
    const float* w_ih0   = (const float*)d_in[7];
    const float* w_hh0   = (const float*)d_in[8];
    const float* b_ih0   = (const float*)d_in[9];
    const float* b_hh0   = (const float*)d_in[10];
    const float* w_ih1   = (const float*)d_in[11];
    const float* w_hh1   = (const float*)d_in[12];
    const float* b_ih1   = (const float*)d_in[13];
    const float* b_hh1   = (const float*)d_in[14];
    const float* w_ih2   = (const float*)d_in[15];
    const float* w_hh2   = (const float*)d_in[16];
    const float* b_ih2   = (const float*)d_in[17];
    const float* b_hh2   = (const float*)d_in[18];
    const float* wc      = (const float*)d_in[19];
    const float* bc      = (const float*)d_in[20];
    const float* wh      = (const float*)d_in[21];
    const float* bh      = (const float*)d_in[22];
    const float* wa      = (const float*)d_in[23];
    const float* ba      = (const float*)d_in[24];

    float* out = (float*)d_out;
    float* h2o = out;            // h2: [B,H]
    float* nh  = out + BH;       // new_h: 3 x [B,H]
    float* nc  = out + 4 * BH;   // new_c: 3 x [B,H]

    dim3 ggrid(G4H / 64, BB / 64);   // (32, 8)

    k_vbias<<<(G4H * 32) / 256, 256>>>(video, w_ih0, b_ih0, b_hh0);

    // layer 0
    k_gemm3_tf32<<<ggrid, 128>>>(
        xt, 512,               w_ih0, 1536,
        state_h + 2 * BH, 512, w_ih0 + 1024, 1536,
        state_h, 512,          w_hh0, 512,
        b_ih0, b_hh0, /*a0_mode=*/0, /*bias_mode=*/1);
    k_lstm_act<<<BH / 256, 256>>>(state_c, nh, nc, nullptr);

    // layer 1
    k_gemm3_tf32<<<ggrid, 128>>>(
        event, 512,            w_ih1, 1024,
        nh, 512,               w_ih1 + 512, 1024,
        state_h + BH, 512,     w_hh1, 512,
        b_ih1, b_hh1, 0, 0);
    k_lstm_act<<<BH / 256, 256>>>(state_c + BH, nh + BH, nc + BH, nullptr);

    // attention
    k_atth<<<BB, 128>>>(nh + BH, wh, bh);
    k_att_scores<<<(BB * LL) / 64, 256>>>(clip, wc, bc, wa, ba);
    k_softmax<<<BB, 256>>>(cmask);
    k_attres<<<BB, 256>>>(clip);

    // layer 2
    k_gemm3_tf32<<<ggrid, 128>>>(
        nullptr, 512,          w_ih2, 1024,
        nh + BH, 512,          w_ih2 + 512, 1024,
        state_h + 2 * BH, 512, w_hh2, 512,
        b_ih2, b_hh2, /*a0_mode=*/1, 0);
    k_lstm_act<<<BH / 256, 256>>>(state_c + 2 * BH, nh + 2 * BH, nc + 2 * BH, h2o);
}

// round 11
// speedup vs baseline: 1.4070x; 1.4070x over previous
#include <cuda_runtime.h>
#include <math.h>
#include <stdint.h>

#define BB   512
#define LL   256
#define HH   512
#define AD   128
#define CD   512
#define G4H  2048      // 4*H
#define BH   (BB*HH)   // 262144

// ---------------- device scratch ----------------
__device__ alignas(16) float g_gates[BB * G4H];     // 4 MB
__device__ alignas(16) float g_vbias[G4H];
__device__ alignas(16) float g_atth[BB * AD];
__device__ alignas(16) float g_scores[BB * LL];
__device__ alignas(16) float g_weight[BB * LL];
__device__ alignas(16) float g_attres[BB * CD];

__device__ __forceinline__ float sigf(float x) { return 1.0f / (1.0f + expf(-x)); }

__device__ __forceinline__ float tanh_ap(float x) {
    float y;
    asm("tanh.approx.f32 %0, %1;" : "=f"(y) : "f"(x));
    return y;
}

// D += A*B, m16n8k8 tf32 (raw fp32 bits -> HW truncates mantissa)
__device__ __forceinline__ void mma8(float* c, const uint32_t* a, const uint32_t* b) {
    asm volatile("mma.sync.aligned.m16n8k8.row.col.f32.tf32.tf32.f32 "
        "{%0,%1,%2,%3}, {%4,%5,%6,%7}, {%8,%9}, {%0,%1,%2,%3};"
        : "+f"(c[0]), "+f"(c[1]), "+f"(c[2]), "+f"(c[3])
        : "r"(a[0]), "r"(a[1]), "r"(a[2]), "r"(a[3]), "r"(b[0]), "r"(b[1]));
}

__device__ __forceinline__ uint32_t smaddr(const void* p) {
    return (uint32_t)__cvta_generic_to_shared(p);
}
__device__ __forceinline__ void cp16(uint32_t dst, const void* src) {
    asm volatile("cp.async.cg.shared.global [%0], [%1], 16;" :: "r"(dst), "l"(src));
}
__device__ __forceinline__ void cp_commit() { asm volatile("cp.async.commit_group;"); }
template<int N> __device__ __forceinline__ void cp_wait() {
    asm volatile("cp.async.wait_group %0;" :: "n"(N));
}

// ---------------- layer-0 bias: one warp per n, coalesced
__global__ void k_vbias(const float* __restrict__ video,
                        const float* __restrict__ w_ih0,
                        const float* __restrict__ b_ih0,
                        const float* __restrict__ b_hh0) {
    int warp = (blockIdx.x * blockDim.x + threadIdx.x) >> 5;
    int lane = threadIdx.x & 31;
    if (warp >= G4H) return;
    const float* w = w_ih0 + (size_t)warp * 1536 + 512;
    float acc = 0.0f;
    #pragma unroll
    for (int i = 0; i < 16; i++) {
        int k = i * 32 + lane;
        acc += video[k] * w[k];
    }
    #pragma unroll
    for (int o = 16; o > 0; o >>= 1)
        acc += __shfl_xor_sync(0xffffffff, acc, o);
    if (lane == 0) g_vbias[warp] = acc + b_ih0[warp] + b_hh0[warp];
}

// ================= tf32 3-pair NT GEMM — CLOCK CANARY, byte-identical to R6 ======
__device__ __forceinline__ void gemm_pair64(
    const float* __restrict__ Ap, int lda,
    const float* __restrict__ Wp, int ldw,
    int m0, int n0, int tid, int lane, int wm, int wn,
    uint32_t* As, uint32_t* Bs,     // each 3 stages x 64*20
    float acc[2][4][4])
{
    int lrow = tid >> 2;               // 0..31
    int kc   = (tid & 3) * 4;          // 0,4,8,12
    const float* a0p = Ap + (size_t)(m0 + lrow) * lda + kc;
    const float* a1p = Ap + (size_t)(m0 + lrow + 32) * lda + kc;
    const float* b0p = Wp + (size_t)(n0 + lrow) * ldw + kc;
    const float* b1p = Wp + (size_t)(n0 + lrow + 32) * ldw + kc;
    uint32_t sa0 = smaddr(As + lrow * 20 + kc);
    uint32_t sa1 = smaddr(As + (lrow + 32) * 20 + kc);
    uint32_t sb0 = smaddr(Bs + lrow * 20 + kc);
    uint32_t sb1 = smaddr(Bs + (lrow + 32) * 20 + kc);
    const uint32_t SBY = 64 * 20 * 4;  // stage stride bytes

    #pragma unroll
    for (int st = 0; st < 3; st++) {
        int k0 = st * 16;
        cp16(sa0 + st * SBY, a0p + k0);
        cp16(sa1 + st * SBY, a1p + k0);
        cp16(sb0 + st * SBY, b0p + k0);
        cp16(sb1 + st * SBY, b1p + k0);
        cp_commit();
    }

    int stage = 0;
    for (int s = 0; s < 32; s++) {
        cp_wait<2>();
        __syncthreads();
        const uint32_t* Ab = As + stage * 1280;
        const uint32_t* Bb = Bs + stage * 1280;
        #pragma unroll
        for (int kk = 0; kk < 16; kk += 8) {
            uint32_t af[2][4], bf[4][2];
            int ar = wm + (lane >> 2);
            int ac = kk + (lane & 3);
            #pragma unroll
            for (int mt = 0; mt < 2; mt++) {
                int r = ar + mt * 16;
                af[mt][0] = Ab[r * 20 + ac];
                af[mt][1] = Ab[(r + 8) * 20 + ac];
                af[mt][2] = Ab[r * 20 + ac + 4];
                af[mt][3] = Ab[(r + 8) * 20 + ac + 4];
            }
            #pragma unroll
            for (int nt = 0; nt < 4; nt++) {
                int c = wn + nt * 8 + (lane >> 2);
                bf[nt][0] = Bb[c * 20 + ac];
                bf[nt][1] = Bb[c * 20 + ac + 4];
            }
            #pragma unroll
            for (int mt = 0; mt < 2; mt++)
                #pragma unroll
                for (int nt = 0; nt < 4; nt++)
                    mma8(acc[mt][nt], af[mt], bf[nt]);
        }
        __syncthreads();
        if (s < 29) {
            int k0 = (s + 3) * 16;
            cp16(sa0 + stage * SBY, a0p + k0);
            cp16(sa1 + stage * SBY, a1p + k0);
            cp16(sb0 + stage * SBY, b0p + k0);
            cp16(sb1 + stage * SBY, b1p + k0);
        }
        cp_commit();
        stage++; if (stage == 3) stage = 0;
    }
}

__global__ __launch_bounds__(128)
void k_gemm3_tf32(const float* __restrict__ A0, int lda0, const float* __restrict__ W0, int ldw0,
                  const float* __restrict__ A1, int lda1, const float* __restrict__ W1, int ldw1,
                  const float* __restrict__ A2, int lda2, const float* __restrict__ W2, int ldw2,
                  const float* __restrict__ bias0, const float* __restrict__ bias1,
                  int a0_mode, int bias_mode)
{
    __shared__ uint32_t As[3 * 64 * 20];
    __shared__ uint32_t Bs[3 * 64 * 20];
    int tid = threadIdx.x;
    int wid = tid >> 5, lane = tid & 31;
    int m0 = blockIdx.y * 64, n0 = blockIdx.x * 64;
    int wm = (wid >> 1) * 32, wn = (wid & 1) * 32;

    if (a0_mode) A0 = g_attres;

    float acc[2][4][4];
    #pragma unroll
    for (int i = 0; i < 2; i++)
        #pragma unroll
        for (int j = 0; j < 4; j++)
            #pragma unroll
            for (int k = 0; k < 4; k++) acc[i][j][k] = 0.0f;

    gemm_pair64(A0, lda0, W0, ldw0, m0, n0, tid, lane, wm, wn, As, Bs, acc);
    gemm_pair64(A1, lda1, W1, ldw1, m0, n0, tid, lane, wm, wn, As, Bs, acc);
    gemm_pair64(A2, lda2, W2, ldw2, m0, n0, tid, lane, wm, wn, As, Bs, acc);

    #pragma unroll
    for (int mt = 0; mt < 2; mt++) {
        int r = m0 + wm + mt * 16 + (lane >> 2);
        #pragma unroll
        for (int nt = 0; nt < 4; nt++) {
            int c = n0 + wn + nt * 8 + 2 * (lane & 3);
            float b0, b1;
            if (bias_mode) { b0 = g_vbias[c]; b1 = g_vbias[c + 1]; }
            else           { b0 = bias0[c] + bias1[c]; b1 = bias0[c + 1] + bias1[c + 1]; }
            g_gates[(size_t)r * G4H + c]           = acc[mt][nt][0] + b0;
            g_gates[(size_t)r * G4H + c + 1]       = acc[mt][nt][1] + b1;
            g_gates[(size_t)(r + 8) * G4H + c]     = acc[mt][nt][2] + b0;
            g_gates[(size_t)(r + 8) * G4H + c + 1] = acc[mt][nt][3] + b1;
        }
    }
}

// ---------------- LSTM activation: g_gates -> (h, c)
__global__ void k_lstm_act(const float* __restrict__ cprev,
                           float* __restrict__ hout, float* __restrict__ cout,
                           float* __restrict__ hout2) {
    int idx = blockIdx.x * blockDim.x + threadIdx.x;
    if (idx >= BH) return;
    int b = idx / HH, j = idx % HH;
    const float* g = g_gates + (size_t)b * G4H;
    float gi = g[j], gf = g[HH + j], gg = g[2 * HH + j], go = g[3 * HH + j];
    float c = sigf(gf) * cprev[idx] + sigf(gi) * tanhf(gg);
    float h = sigf(go) * tanhf(c);
    hout[idx] = h;
    cout[idx] = c;
    if (hout2) hout2[idx] = h;
}

// ---------------- att_h = h1 @ wh.T + bh  ([B,128])
__global__ void k_atth(const float* __restrict__ h1, const float* __restrict__ wh,
                       const float* __restrict__ bh) {
    __shared__ float hs[512];
    int b = blockIdx.x, t = threadIdx.x;   // 128 threads
    for (int i = t; i < 512; i += 128) hs[i] = h1[(size_t)b * 512 + i];
    __syncthreads();
    const float* w = wh + (size_t)t * 512;
    float acc = bh[t];
    #pragma unroll 8
    for (int k = 0; k < 512; k++) acc += hs[k] * w[k];
    g_atth[b * AD + t] = acc;
}

// ====== fused attention scores v3: 64x128 block, 4 warps (2m x 2n, warp 32x64) ======
// 3-stage cp.async BK16; LDS:MMA = 1.5; 2048 blocks.
__global__ __launch_bounds__(128)
void k_att_scores(const float* __restrict__ clip, const float* __restrict__ wc,
                  const float* __restrict__ bc, const float* __restrict__ wa,
                  const float* __restrict__ ba) {
    __shared__ uint32_t As[3 * 64 * 20];    // 15.0 KB
    __shared__ uint32_t Bs[3 * 128 * 20];   // 30.0 KB
    __shared__ float red[64 * 3];           // 0.75 KB
    __shared__ float addsh[128], wash[128]; // 1 KB   (total 47.9 KB)

    int tid = threadIdx.x;
    int wid = tid >> 5, lane = tid & 31;
    int m0 = blockIdx.x * 64;           // row within [B*L]
    int bidx = blockIdx.x >> 2;         // batch (4 blocks per batch, L=256)
    int wm = (wid >> 1) * 32;           // 0 or 32
    int wn = (wid & 1) * 64;            // 0 or 64

    addsh[tid] = bc[tid] + g_atth[bidx * AD + tid];
    wash[tid] = wa[tid];

    // loaders (128 thr): A 64x16 -> 2 cp16/thr; B 128x16 -> 4 cp16/thr
    int lrowA = tid >> 1;               // 0..63
    int kcA   = (tid & 1) * 8;          // 0 or 8
    int lrowB = tid;                    // 0..127
    const float* apg = clip + (size_t)(m0 + lrowA) * CD + kcA;
    const float* bpg = wc + (size_t)lrowB * CD;
    uint32_t sa = smaddr(As + lrowA * 20 + kcA);
    uint32_t sb = smaddr(Bs + lrowB * 20);
    const uint32_t SA = 64 * 20 * 4, SB = 128 * 20 * 4;

    float acc[2][8][4];
    #pragma unroll
    for (int i = 0; i < 2; i++)
        #pragma unroll
        for (int j = 0; j < 8; j++)
            #pragma unroll
            for (int k = 0; k < 4; k++) acc[i][j][k] = 0.0f;

    #pragma unroll
    for (int st = 0; st < 3; st++) {
        int k0 = st * 16;
        cp16(sa + st * SA, apg + k0);
        cp16(sa + st * SA + 16, apg + k0 + 4);
        cp16(sb + st * SB, bpg + k0);
        cp16(sb + st * SB + 16, bpg + k0 + 4);
        cp16(sb + st * SB + 32, bpg + k0 + 8);
        cp16(sb + st * SB + 48, bpg + k0 + 12);
        cp_commit();
    }

    int stage = 0;
    for (int s = 0; s < 32; s++) {
        cp_wait<2>();
        __syncthreads();
        const uint32_t* Ab = As + stage * 1280;
        const uint32_t* Bb = Bs + stage * 2560;
        #pragma unroll
        for (int kk = 0; kk < 16; kk += 8) {
            uint32_t af[2][4], bf[8][2];
            int ar = wm + (lane >> 2);
            int ac = kk + (lane & 3);
            #pragma unroll
            for (int mt = 0; mt < 2; mt++) {
                int r = ar + mt * 16;
                af[mt][0] = Ab[r * 20 + ac];
                af[mt][1] = Ab[(r + 8) * 20 + ac];
                af[mt][2] = Ab[r * 20 + ac + 4];
                af[mt][3] = Ab[(r + 8) * 20 + ac + 4];
            }
            #pragma unroll
            for (int nt = 0; nt < 8; nt++) {
                int c = wn + nt * 8 + (lane >> 2);
                bf[nt][0] = Bb[c * 20 + ac];
                bf[nt][1] = Bb[c * 20 + ac + 4];
            }
            #pragma unroll
            for (int mt = 0; mt < 2; mt++)
                #pragma unroll
                for (int nt = 0; nt < 8; nt++)
                    mma8(acc[mt][nt], af[mt], bf[nt]);
        }
        __syncthreads();
        if (s < 29) {
            int k0 = (s + 3) * 16;
            cp16(sa + stage * SA, apg + k0);
            cp16(sa + stage * SA + 16, apg + k0 + 4);
            cp16(sb + stage * SB, bpg + k0);
            cp16(sb + stage * SB + 16, bpg + k0 + 4);
            cp16(sb + stage * SB + 32, bpg + k0 + 8);
            cp16(sb + stage * SB + 48, bpg + k0 + 12);
        }
        cp_commit();
        stage++; if (stage == 3) stage = 0;
    }

    // epilogue: HW tanh + dot with wa; reduce within quad, then across 2 n-warps
    float ps[2][2] = {{0.0f, 0.0f}, {0.0f, 0.0f}};
    #pragma unroll
    for (int mt = 0; mt < 2; mt++) {
        #pragma unroll
        for (int nt = 0; nt < 8; nt++) {
            int c = wn + nt * 8 + 2 * (lane & 3);
            float a0 = addsh[c], a1 = addsh[c + 1];
            float w0 = wash[c], w1 = wash[c + 1];
            float t0 = tanh_ap(acc[mt][nt][0] + a0);
            float t1 = tanh_ap(acc[mt][nt][1] + a1);
            float t2 = tanh_ap(acc[mt][nt][2] + a0);
            float t3 = tanh_ap(acc[mt][nt][3] + a1);
            ps[mt][0] += t0 * w0 + t1 * w1;
            ps[mt][1] += t2 * w0 + t3 * w1;
        }
    }
    #pragma unroll
    for (int o = 1; o <= 2; o <<= 1) {
        ps[0][0] += __shfl_xor_sync(0xffffffff, ps[0][0], o);
        ps[0][1] += __shfl_xor_sync(0xffffffff, ps[0][1], o);
        ps[1][0] += __shfl_xor_sync(0xffffffff, ps[1][0], o);
        ps[1][1] += __shfl_xor_sync(0xffffffff, ps[1][1], o);
    }
    if ((lane & 3) == 0) {
        int wq = wid & 1;               // n-warp index 0..1
        int lq = lane >> 2;             // 0..7
        #pragma unroll
        for (int mt = 0; mt < 2; mt++) {
            int r = wm + mt * 16 + lq;
            red[r * 3 + wq] = ps[mt][0];
            red[(r + 8) * 3 + wq] = ps[mt][1];
        }
    }
    __syncthreads();
    if (tid < 64) {
        g_scores[m0 + tid] = ba[0] + red[tid * 3] + red[tid * 3 + 1];
    }
}

// ---------------- masked softmax + renorm (per batch row, L=256)
__global__ void k_softmax(const int* __restrict__ mask) {
    __shared__ float sh[256];
    int b = blockIdx.x, t = threadIdx.x;
    float s = g_scores[b * LL + t];
    sh[t] = s;
    __syncthreads();
    for (int o = 128; o > 0; o >>= 1) {
        if (t < o) sh[t] = fmaxf(sh[t], sh[t + o]);
        __syncthreads();
    }
    float mx = sh[0];
    __syncthreads();
    float p = expf(s - mx);
    float pm = p * (float)mask[b * LL + t];
    sh[t] = pm;
    __syncthreads();
    for (int o = 128; o > 0; o >>= 1) {
        if (t < o) sh[t] += sh[t + o];
        __syncthreads();
    }
    float denom = sh[0];
    g_weight[b * LL + t] = pm / denom;
}

// ---------------- att_res[b,c] = sum_l weight[b,l]*clip[b,l,c], 2 L-halves, 256 thr
__global__ void k_attres(const float* __restrict__ clip) {
    __shared__ float w[256];
    __shared__ float part[512];
    int b = blockIdx.x, t = threadIdx.x;   // 256 threads
    w[t] = g_weight[b * LL + t];
    __syncthreads();
    int half = t >> 7, tt = t & 127;
    const float* cb = clip + (size_t)b * LL * CD + (size_t)half * 128 * CD;
    const float* wl = w + half * 128;
    float4 a = make_float4(0.0f, 0.0f, 0.0f, 0.0f);
    #pragma unroll 4
    for (int l = 0; l < 128; l++) {
        float wv = wl[l];
        float4 v = *reinterpret_cast<const float4*>(cb + (size_t)l * CD + tt * 4);
        a.x += wv * v.x; a.y += wv * v.y; a.z += wv * v.z; a.w += wv * v.w;
    }
    if (half) *reinterpret_cast<float4*>(&part[tt * 4]) = a;
    __syncthreads();
    if (!half) {
        float4 p = *reinterpret_cast<const float4*>(&part[tt * 4]);
        a.x += p.x; a.y += p.y; a.z += p.z; a.w += p.w;
        *reinterpret_cast<float4*>(&g_attres[b * CD + tt * 4]) = a;
    }
}

// ---------------- launch ----------------
extern "C" void kernel_launch(void* const* d_in, const int* in_sizes, int n_in,
                              void* d_out, int out_size) {
    const float* xt      = (const float*)d_in[0];
    const float* video   = (const float*)d_in[1];
    const float* event   = (const float*)d_in[2];
    const float* clip    = (const float*)d_in[3];
    const int*   cmask   = (const int*)d_in[4];
    const float* state_h = (const float*)d_in[5];
    const float* state_c = (const float*)d_in[6];
    const float* w_ih0   = (const float*)d_in[7];
    const float* w_hh0   = (const float*)d_in[8];
    const float* b_ih0   = (const float*)d_in[9];
    const float* b_hh0   = (const float*)d_in[10];
    const float* w_ih1   = (const float*)d_in[11];
    const float* w_hh1   = (const float*)d_in[12];
    const float* b_ih1   = (const float*)d_in[13];
    const float* b_hh1   = (const float*)d_in[14];
    const float* w_ih2   = (const float*)d_in[15];
    const float* w_hh2   = (const float*)d_in[16];
    const float* b_ih2   = (const float*)d_in[17];
    const float* b_hh2   = (const float*)d_in[18];
    const float* wc      = (const float*)d_in[19];
    const float* bc      = (const float*)d_in[20];
    const float* wh      = (const float*)d_in[21];
    const float* bh      = (const float*)d_in[22];
    const float* wa      = (const float*)d_in[23];
    const float* ba      = (const float*)d_in[24];

    float* out = (float*)d_out;
    float* h2o = out;            // h2: [B,H]
    float* nh  = out + BH;       // new_h: 3 x [B,H]
    float* nc  = out + 4 * BH;   // new_c: 3 x [B,H]

    dim3 ggrid(G4H / 64, BB / 64);   // (32, 8)

    k_vbias<<<(G4H * 32) / 256, 256>>>(video, w_ih0, b_ih0, b_hh0);

    // layer 0
    k_gemm3_tf32<<<ggrid, 128>>>(
        xt, 512,               w_ih0, 1536,
        state_h + 2 * BH, 512, w_ih0 + 1024, 1536,
        state_h, 512,          w_hh0, 512,
        b_ih0, b_hh0, /*a0_mode=*/0, /*bias_mode=*/1);
    k_lstm_act<<<BH / 256, 256>>>(state_c, nh, nc, nullptr);

    // layer 1
    k_gemm3_tf32<<<ggrid, 128>>>(
        event, 512,            w_ih1, 1024,
        nh, 512,               w_ih1 + 512, 1024,
        state_h + BH, 512,     w_hh1, 512,
        b_ih1, b_hh1, 0, 0);
    k_lstm_act<<<BH / 256, 256>>>(state_c + BH, nh + BH, nc + BH, nullptr);

    // attention
    k_atth<<<BB, 128>>>(nh + BH, wh, bh);
    k_att_scores<<<(BB * LL) / 64, 128>>>(clip, wc, bc, wa, ba);
    k_softmax<<<BB, 256>>>(cmask);
    k_attres<<<BB, 256>>>(clip);

    // layer 2
    k_gemm3_tf32<<<ggrid, 128>>>(
        nullptr, 512,          w_ih2, 1024,
        nh + BH, 512,          w_ih2 + 512, 1024,
        state_h + 2 * BH, 512, w_hh2, 512,
        b_ih2, b_hh2, /*a0_mode=*/1, 0);
    k_lstm_act<<<BH / 256, 256>>>(state_c + 2 * BH, nh + 2 * BH, nc + 2 * BH, h2o);
}

// round 14
// speedup vs baseline: 1.7532x; 1.2461x over previous
#include <cuda_runtime.h>
#include <cuda_fp16.h>
#include <math.h>
#include <stdint.h>

#define BB   512
#define LL   256
#define HH   512
#define AD   128
#define CD   512
#define G4H  2048      // 4*H
#define BH   (BB*HH)   // 262144

// ---------------- fp32 device scratch ----------------
__device__ alignas(16) float g_gates[BB * G4H];     // 4 MB
__device__ alignas(16) float g_vbias[G4H];
__device__ alignas(16) float g_atth[BB * AD];
__device__ alignas(16) float g_scores[BB * LL];
__device__ alignas(16) float g_weight[BB * LL];

// ---------------- fp16 buffers ----------------
__device__ alignas(16) __half g_wih0h[2048 * 1536];
__device__ alignas(16) __half g_whh0h[2048 * 512];
__device__ alignas(16) __half g_wih1h[2048 * 1024];
__device__ alignas(16) __half g_whh1h[2048 * 512];
__device__ alignas(16) __half g_wih2h[2048 * 1024];
__device__ alignas(16) __half g_whh2h[2048 * 512];
__device__ alignas(16) __half g_wch[128 * 512];
__device__ alignas(16) __half g_cliph[(size_t)BB * LL * CD];   // 67 MB
__device__ alignas(16) __half g_xth[BB * 512];
__device__ alignas(16) __half g_eventh[BB * 512];
__device__ alignas(16) __half g_sh0h[BH];
__device__ alignas(16) __half g_sh1h[BH];
__device__ alignas(16) __half g_sh2h[BH];
__device__ alignas(16) __half g_h0h[BH];
__device__ alignas(16) __half g_h1h[BH];
__device__ alignas(16) __half g_attresh[BB * CD];

__device__ __forceinline__ float sigf(float x) { return 1.0f / (1.0f + expf(-x)); }

__device__ __forceinline__ float tanh_ap(float x) {
    float y;
    asm("tanh.approx.f32 %0, %1;" : "=f"(y) : "f"(x));
    return y;
}

// D += A*B, m16n8k16 fp16 inputs, fp32 accumulate
__device__ __forceinline__ void mma16(float* c, const uint32_t* a, const uint32_t* b) {
    asm volatile("mma.sync.aligned.m16n8k16.row.col.f32.f16.f16.f32 "
        "{%0,%1,%2,%3}, {%4,%5,%6,%7}, {%8,%9}, {%0,%1,%2,%3};"
        : "+f"(c[0]), "+f"(c[1]), "+f"(c[2]), "+f"(c[3])
        : "r"(a[0]), "r"(a[1]), "r"(a[2]), "r"(a[3]), "r"(b[0]), "r"(b[1]));
}

__device__ __forceinline__ void ldsm4(uint32_t* r, uint32_t saddr) {
    asm volatile("ldmatrix.sync.aligned.m8n8.x4.shared.b16 {%0,%1,%2,%3}, [%4];"
        : "=r"(r[0]), "=r"(r[1]), "=r"(r[2]), "=r"(r[3]) : "r"(saddr));
}

__device__ __forceinline__ uint32_t smaddr(const void* p) {
    return (uint32_t)__cvta_generic_to_shared(p);
}
__device__ __forceinline__ void cp16(uint32_t dst, const void* src) {
    asm volatile("cp.async.cg.shared.global [%0], [%1], 16;" :: "r"(dst), "l"(src));
}
__device__ __forceinline__ void cp_commit() { asm volatile("cp.async.commit_group;"); }
template<int N> __device__ __forceinline__ void cp_wait() {
    asm volatile("cp.async.wait_group %0;" :: "n"(N));
}

// ---------------- fp32 -> fp16 conversion (dst selected by id; device globals)
__device__ __forceinline__ __half* f2h_dst(int id) {
    switch (id) {
        case 0: return g_wih0h;  case 1: return g_whh0h;
        case 2: return g_wih1h;  case 3: return g_whh1h;
        case 4: return g_wih2h;  case 5: return g_whh2h;
        case 6: return g_wch;    case 7: return g_cliph;
        case 8: return g_xth;    case 9: return g_eventh;
        case 10: return g_sh0h;  case 11: return g_sh1h;
        default: return g_sh2h;
    }
}
__global__ void k_f2h(const float* __restrict__ src, int id, int n4) {
    int i = blockIdx.x * blockDim.x + threadIdx.x;
    if (i >= n4) return;
    float4 v = reinterpret_cast<const float4*>(src)[i];
    __half2 h0 = __floats2half2_rn(v.x, v.y);
    __half2 h1 = __floats2half2_rn(v.z, v.w);
    uint2 o;
    o.x = *reinterpret_cast<uint32_t*>(&h0);
    o.y = *reinterpret_cast<uint32_t*>(&h1);
    reinterpret_cast<uint2*>(f2h_dst(id))[i] = o;
}
#define F2H(src, id, n4) k_f2h<<<((n4) + 255) / 256, 256>>>((src), (id), (n4))

// ---------------- layer-0 bias: one warp per n, coalesced (fp32)
__global__ void k_vbias(const float* __restrict__ video,
                        const float* __restrict__ w_ih0,
                        const float* __restrict__ b_ih0,
                        const float* __restrict__ b_hh0) {
    int warp = (blockIdx.x * blockDim.x + threadIdx.x) >> 5;
    int lane = threadIdx.x & 31;
    if (warp >= G4H) return;
    const float* w = w_ih0 + (size_t)warp * 1536 + 512;
    float acc = 0.0f;
    #pragma unroll
    for (int i = 0; i < 16; i++) {
        int k = i * 32 + lane;
        acc += video[k] * w[k];
    }
    #pragma unroll
    for (int o = 16; o > 0; o >>= 1)
        acc += __shfl_xor_sync(0xffffffff, acc, o);
    if (lane == 0) g_vbias[warp] = acc + b_ih0[warp] + b_hh0[warp];
}

// ====== fp16 3-pair NT GEMM: g_gates = sum_p A_p @ W_p^T + bias ======
// 64x64 tile, BK=32 halves, 128 thr (4 warps 2x2, warp 32x32), 3-stage cp.async + LDSM.
__device__ __forceinline__ void gemm_pair_h(
    const __half* __restrict__ Ap, int lda,
    const __half* __restrict__ Wp, int ldw,
    int m0, int n0, int tid, int lane, int wm, int wn,
    __half* As, __half* Bs, float acc[2][4][4])
{
    int lrow = tid >> 1;                 // 0..63
    int kh   = (tid & 1) * 16;           // half-offset 0 or 16
    const __half* apg = Ap + (size_t)(m0 + lrow) * lda + kh;
    const __half* bpg = Wp + (size_t)(n0 + lrow) * ldw + kh;
    uint32_t sa = smaddr(As + lrow * 40 + kh);
    uint32_t sb = smaddr(Bs + lrow * 40 + kh);
    const uint32_t SBY = 64 * 40 * 2;    // 5120 B per stage

    // LDSM source offsets (bytes) within a stage
    uint32_t aoff[2], boff[2];
    {
        int arow = lane & 15, akb = lane >> 4;
        #pragma unroll
        for (int mt = 0; mt < 2; mt++)
            aoff[mt] = (uint32_t)(((wm + mt * 16 + arow) * 40 + akb * 8) * 2);
        int bn = (lane & 7) + ((lane >> 4) << 3), bkb = (lane >> 3) & 1;
        #pragma unroll
        for (int nt = 0; nt < 2; nt++)
            boff[nt] = (uint32_t)(((wn + nt * 16 + bn) * 40 + bkb * 8) * 2);
    }
    uint32_t asb = smaddr(As), bsb = smaddr(Bs);

    #pragma unroll
    for (int st = 0; st < 3; st++) {
        int k0 = st * 32;
        cp16(sa + st * SBY, apg + k0);
        cp16(sa + st * SBY + 16, apg + k0 + 8);
        cp16(sb + st * SBY, bpg + k0);
        cp16(sb + st * SBY + 16, bpg + k0 + 8);
        cp_commit();
    }

    int stage = 0;
    for (int s = 0; s < 16; s++) {
        cp_wait<2>();
        __syncthreads();
        uint32_t ab = asb + stage * SBY;
        uint32_t bb = bsb + stage * SBY;
        #pragma unroll
        for (int kk = 0; kk < 2; kk++) {
            uint32_t af[2][4], bq[2][4];
            ldsm4(af[0], ab + aoff[0] + kk * 32);
            ldsm4(af[1], ab + aoff[1] + kk * 32);
            ldsm4(bq[0], bb + boff[0] + kk * 32);
            ldsm4(bq[1], bb + boff[1] + kk * 32);
            #pragma unroll
            for (int mt = 0; mt < 2; mt++)
                #pragma unroll
                for (int j = 0; j < 4; j++)
                    mma16(acc[mt][j], af[mt], &bq[j >> 1][(j & 1) * 2]);
        }
        __syncthreads();
        if (s < 13) {
            int k0 = (s + 3) * 32;
            cp16(sa + stage * SBY, apg + k0);
            cp16(sa + stage * SBY + 16, apg + k0 + 8);
            cp16(sb + stage * SBY, bpg + k0);
            cp16(sb + stage * SBY + 16, bpg + k0 + 8);
        }
        cp_commit();
        stage++; if (stage == 3) stage = 0;
    }
}

__global__ __launch_bounds__(128)
void k_gemm3_h(int layer, const float* __restrict__ bias0,
               const float* __restrict__ bias1, int bias_mode)
{
    __shared__ __half As[3 * 64 * 40];
    __shared__ __half Bs[3 * 64 * 40];
    int tid = threadIdx.x;
    int wid = tid >> 5, lane = tid & 31;
    int m0 = blockIdx.y * 64, n0 = blockIdx.x * 64;
    int wm = (wid >> 1) * 32, wn = (wid & 1) * 32;

    const __half *A0, *A1, *A2, *W0, *W1, *W2;
    int ldw0, ldw1, ldw2;
    if (layer == 0) {
        A0 = g_xth; A1 = g_sh2h; A2 = g_sh0h;
        W0 = g_wih0h; ldw0 = 1536; W1 = g_wih0h + 1024; ldw1 = 1536;
        W2 = g_whh0h; ldw2 = 512;
    } else if (layer == 1) {
        A0 = g_eventh; A1 = g_h0h; A2 = g_sh1h;
        W0 = g_wih1h; ldw0 = 1024; W1 = g_wih1h + 512; ldw1 = 1024;
        W2 = g_whh1h; ldw2 = 512;
    } else {
        A0 = g_attresh; A1 = g_h1h; A2 = g_sh2h;
        W0 = g_wih2h; ldw0 = 1024; W1 = g_wih2h + 512; ldw1 = 1024;
        W2 = g_whh2h; ldw2 = 512;
    }

    float acc[2][4][4];
    #pragma unroll
    for (int i = 0; i < 2; i++)
        #pragma unroll
        for (int j = 0; j < 4; j++)
            #pragma unroll
            for (int k = 0; k < 4; k++) acc[i][j][k] = 0.0f;

    gemm_pair_h(A0, 512, W0, ldw0, m0, n0, tid, lane, wm, wn, As, Bs, acc);
    gemm_pair_h(A1, 512, W1, ldw1, m0, n0, tid, lane, wm, wn, As, Bs, acc);
    gemm_pair_h(A2, 512, W2, ldw2, m0, n0, tid, lane, wm, wn, As, Bs, acc);

    #pragma unroll
    for (int mt = 0; mt < 2; mt++) {
        int r = m0 + wm + mt * 16 + (lane >> 2);
        #pragma unroll
        for (int nt = 0; nt < 4; nt++) {
            int c = n0 + wn + nt * 8 + 2 * (lane & 3);
            float b0, b1;
            if (bias_mode) { b0 = g_vbias[c]; b1 = g_vbias[c + 1]; }
            else           { b0 = bias0[c] + bias1[c]; b1 = bias0[c + 1] + bias1[c + 1]; }
            g_gates[(size_t)r * G4H + c]           = acc[mt][nt][0] + b0;
            g_gates[(size_t)r * G4H + c + 1]       = acc[mt][nt][1] + b1;
            g_gates[(size_t)(r + 8) * G4H + c]     = acc[mt][nt][2] + b0;
            g_gates[(size_t)(r + 8) * G4H + c + 1] = acc[mt][nt][3] + b1;
        }
    }
}

// ---------------- LSTM activation: g_gates -> (h, c); optionally writes fp16 h copy
__global__ void k_lstm_act(const float* __restrict__ cprev,
                           float* __restrict__ hout, float* __restrict__ cout,
                           float* __restrict__ hout2, int hsel) {
    int idx = blockIdx.x * blockDim.x + threadIdx.x;
    if (idx >= BH) return;
    int b = idx / HH, j = idx % HH;
    const float* g = g_gates + (size_t)b * G4H;
    float gi = g[j], gf = g[HH + j], gg = g[2 * HH + j], go = g[3 * HH + j];
    float c = sigf(gf) * cprev[idx] + sigf(gi) * tanhf(gg);
    float h = sigf(go) * tanhf(c);
    hout[idx] = h;
    cout[idx] = c;
    if (hout2) hout2[idx] = h;
    if (hsel == 0) g_h0h[idx] = __float2half_rn(h);
    else if (hsel == 1) g_h1h[idx] = __float2half_rn(h);
}

// ---------------- att_h = h1 @ wh.T + bh  ([B,128], fp32)
__global__ void k_atth(const float* __restrict__ h1, const float* __restrict__ wh,
                       const float* __restrict__ bh) {
    __shared__ float hs[512];
    int b = blockIdx.x, t = threadIdx.x;   // 128 threads
    for (int i = t; i < 512; i += 128) hs[i] = h1[(size_t)b * 512 + i];
    __syncthreads();
    const float* w = wh + (size_t)t * 512;
    float acc = bh[t];
    #pragma unroll 8
    for (int k = 0; k < 512; k++) acc += hs[k] * w[k];
    g_atth[b * AD + t] = acc;
}

// ====== fp16 fused attention scores: 64x128 block, 8 warps (2m x 4n, warp 32x32) ======
// A = g_cliph rows, B = g_wch; BK=32 halves, 3-stage cp.async + LDSM + m16n8k16.
__global__ __launch_bounds__(256)
void k_att_h(const float* __restrict__ bc, const float* __restrict__ wa,
             const float* __restrict__ ba) {
    __shared__ __half As[3 * 64 * 40];      // 15360 B
    __shared__ __half Bs[3 * 128 * 40];     // 30720 B
    __shared__ float red[64 * 5];           // 1280 B
    __shared__ float addsh[128], wash[128]; // 1024 B

    int tid = threadIdx.x;
    int wid = tid >> 5, lane = tid & 31;
    int m0 = blockIdx.x * 64;           // row within [B*L]
    int bidx = blockIdx.x >> 2;         // batch (4 blocks per batch)
    int wm = (wid >> 2) * 32;           // 0 or 32
    int wn = (wid & 3) * 32;            // 0,32,64,96

    if (tid < 128) {
        addsh[tid] = bc[tid] + g_atth[bidx * AD + tid];
        wash[tid] = wa[tid];
    }

    // loaders: A 64 rows x 32 halves -> 1 cp16/thr; B 128 rows -> 2 cp16/thr
    int lrowA = tid >> 2;               // 0..63
    int kcA   = (tid & 3) * 8;          // halves 0,8,16,24
    int lrowB = tid >> 1;               // 0..127
    int kcB   = (tid & 1) * 16;         // halves 0 or 16
    const __half* apg = g_cliph + (size_t)(m0 + lrowA) * CD + kcA;
    const __half* bpg = g_wch + (size_t)lrowB * 512 + kcB;
    uint32_t sa = smaddr(As + lrowA * 40 + kcA);
    uint32_t sb = smaddr(Bs + lrowB * 40 + kcB);
    const uint32_t SA = 64 * 40 * 2, SB = 128 * 40 * 2;

    uint32_t aoff[2], boff[2];
    {
        int arow = lane & 15, akb = lane >> 4;
        #pragma unroll
        for (int mt = 0; mt < 2; mt++)
            aoff[mt] = (uint32_t)(((wm + mt * 16 + arow) * 40 + akb * 8) * 2);
        int bn = (lane & 7) + ((lane >> 4) << 3), bkb = (lane >> 3) & 1;
        #pragma unroll
        for (int nt = 0; nt < 2; nt++)
            boff[nt] = (uint32_t)(((wn + nt * 16 + bn) * 40 + bkb * 8) * 2);
    }
    uint32_t asb = smaddr(As), bsb = smaddr(Bs);

    float acc[2][4][4];
    #pragma unroll
    for (int i = 0; i < 2; i++)
        #pragma unroll
        for (int j = 0; j < 4; j++)
            #pragma unroll
            for (int k = 0; k < 4; k++) acc[i][j][k] = 0.0f;

    #pragma unroll
    for (int st = 0; st < 3; st++) {
        int k0 = st * 32;
        cp16(sa + st * SA, apg + k0);
        cp16(sb + st * SB, bpg + k0);
        cp16(sb + st * SB + 16, bpg + k0 + 8);
        cp_commit();
    }

    int stage = 0;
    for (int s = 0; s < 16; s++) {
        cp_wait<2>();
        __syncthreads();
        uint32_t ab = asb + stage * SA;
        uint32_t bb = bsb + stage * SB;
        #pragma unroll
        for (int kk = 0; kk < 2; kk++) {
            uint32_t af[2][4], bq[2][4];
            ldsm4(af[0], ab + aoff[0] + kk * 32);
            ldsm4(af[1], ab + aoff[1] + kk * 32);
            ldsm4(bq[0], bb + boff[0] + kk * 32);
            ldsm4(bq[1], bb + boff[1] + kk * 32);
            #pragma unroll
            for (int mt = 0; mt < 2; mt++)
                #pragma unroll
                for (int j = 0; j < 4; j++)
                    mma16(acc[mt][j], af[mt], &bq[j >> 1][(j & 1) * 2]);
        }
        __syncthreads();
        if (s < 13) {
            int k0 = (s + 3) * 32;
            cp16(sa + stage * SA, apg + k0);
            cp16(sb + stage * SB, bpg + k0);
            cp16(sb + stage * SB + 16, bpg + k0 + 8);
        }
        cp_commit();
        stage++; if (stage == 3) stage = 0;
    }

    // epilogue: HW tanh + dot with wa; in-quad shuffle, then cross-n-warp reduce
    float ps[2][2] = {{0.0f, 0.0f}, {0.0f, 0.0f}};
    #pragma unroll
    for (int mt = 0; mt < 2; mt++) {
        #pragma unroll
        for (int nt = 0; nt < 4; nt++) {
            int c = wn + nt * 8 + 2 * (lane & 3);
            float a0 = addsh[c], a1 = addsh[c + 1];
            float w0 = wash[c], w1 = wash[c + 1];
            float t0 = tanh_ap(acc[mt][nt][0] + a0);
            float t1 = tanh_ap(acc[mt][nt][1] + a1);
            float t2 = tanh_ap(acc[mt][nt][2] + a0);
            float t3 = tanh_ap(acc[mt][nt][3] + a1);
            ps[mt][0] += t0 * w0 + t1 * w1;
            ps[mt][1] += t2 * w0 + t3 * w1;
        }
    }
    #pragma unroll
    for (int o = 1; o <= 2; o <<= 1) {
        ps[0][0] += __shfl_xor_sync(0xffffffff, ps[0][0], o);
        ps[0][1] += __shfl_xor_sync(0xffffffff, ps[0][1], o);
        ps[1][0] += __shfl_xor_sync(0xffffffff, ps[1][0], o);
        ps[1][1] += __shfl_xor_sync(0xffffffff, ps[1][1], o);
    }
    if ((lane & 3) == 0) {
        int wq = wid & 3;
        int lq = lane >> 2;
        #pragma unroll
        for (int mt = 0; mt < 2; mt++) {
            int r = wm + mt * 16 + lq;
            red[r * 5 + wq] = ps[mt][0];
            red[(r + 8) * 5 + wq] = ps[mt][1];
        }
    }
    __syncthreads();
    if (tid < 64) {
        g_scores[m0 + tid] = ba[0] + red[tid * 5] + red[tid * 5 + 1]
                           + red[tid * 5 + 2] + red[tid * 5 + 3];
    }
}

// ---------------- masked softmax + renorm (per batch row, L=256)
__global__ void k_softmax(const int* __restrict__ mask) {
    __shared__ float sh[256];
    int b = blockIdx.x, t = threadIdx.x;
    float s = g_scores[b * LL + t];
    sh[t] = s;
    __syncthreads();
    for (int o = 128; o > 0; o >>= 1) {
        if (t < o) sh[t] = fmaxf(sh[t], sh[t + o]);
        __syncthreads();
    }
    float mx = sh[0];
    __syncthreads();
    float p = expf(s - mx);
    float pm = p * (float)mask[b * LL + t];
    sh[t] = pm;
    __syncthreads();
    for (int o = 128; o > 0; o >>= 1) {
        if (t < o) sh[t] += sh[t + o];
        __syncthreads();
    }
    float denom = sh[0];
    g_weight[b * LL + t] = pm / denom;
}

// ---------------- att_res[b,c] = sum_l weight[b,l]*clip[b,l,c] from fp16 clip;
// writes fp16 att_res for layer-2 GEMM. 256 thr, 2 L-halves.
__global__ void k_attres() {
    __shared__ float w[256];
    __shared__ float part[512];
    int b = blockIdx.x, t = threadIdx.x;
    w[t] = g_weight[b * LL + t];
    __syncthreads();
    int half_ = t >> 7, tt = t & 127;
    const __half* cb = g_cliph + (size_t)b * LL * CD + (size_t)half_ * 128 * CD;
    const float* wl = w + half_ * 128;
    float a0 = 0.0f, a1 = 0.0f, a2 = 0.0f, a3 = 0.0f;
    #pragma unroll 4
    for (int l = 0; l < 128; l++) {
        float wv = wl[l];
        uint2 u = *reinterpret_cast<const uint2*>(cb + (size_t)l * CD + tt * 4);
        __half2 h0 = *reinterpret_cast<__half2*>(&u.x);
        __half2 h1 = *reinterpret_cast<__half2*>(&u.y);
        float2 f0 = __half22float2(h0);
        float2 f1 = __half22float2(h1);
        a0 += wv * f0.x; a1 += wv * f0.y; a2 += wv * f1.x; a3 += wv * f1.y;
    }
    if (half_) {
        part[tt * 4] = a0; part[tt * 4 + 1] = a1; part[tt * 4 + 2] = a2; part[tt * 4 + 3] = a3;
    }
    __syncthreads();
    if (!half_) {
        a0 += part[tt * 4]; a1 += part[tt * 4 + 1]; a2 += part[tt * 4 + 2]; a3 += part[tt * 4 + 3];
        __half2 h0 = __floats2half2_rn(a0, a1);
        __half2 h1 = __floats2half2_rn(a2, a3);
        uint2 o;
        o.x = *reinterpret_cast<uint32_t*>(&h0);
        o.y = *reinterpret_cast<uint32_t*>(&h1);
        *reinterpret_cast<uint2*>(&g_attresh[b * CD + tt * 4]) = o;
    }
}

// ---------------- launch ----------------
extern "C" void kernel_launch(void* const* d_in, const int* in_sizes, int n_in,
                              void* d_out, int out_size) {
    const float* xt      = (const float*)d_in[0];
    const float* video   = (const float*)d_in[1];
    const float* event   = (const float*)d_in[2];
    const float* clip    = (const float*)d_in[3];
    const int*   cmask   = (const int*)d_in[4];
    const float* state_h = (const float*)d_in[5];
    const float* state_c = (const float*)d_in[6];
    const float* w_ih0   = (const float*)d_in[7];
    const float* w_hh0   = (const float*)d_in[8];
    const float* b_ih0   = (const float*)d_in[9];
    const float* b_hh0   = (const float*)d_in[10];
    const float* w_ih1   = (const float*)d_in[11];
    const float* w_hh1   = (const float*)d_in[12];
    const float* b_ih1   = (const float*)d_in[13];
    const float* b_hh1   = (const float*)d_in[14];
    const float* w_ih2   = (const float*)d_in[15];
    const float* w_hh2   = (const float*)d_in[16];
    const float* b_ih2   = (const float*)d_in[17];
    const float* b_hh2   = (const float*)d_in[18];
    const float* wc      = (const float*)d_in[19];
    const float* bc      = (const float*)d_in[20];
    const float* wh      = (const float*)d_in[21];
    const float* bh      = (const float*)d_in[22];
    const float* wa      = (const float*)d_in[23];
    const float* ba      = (const float*)d_in[24];

    float* out = (float*)d_out;
    float* h2o = out;            // h2: [B,H]
    float* nh  = out + BH;       // new_h: 3 x [B,H]
    float* nc  = out + 4 * BH;   // new_c: 3 x [B,H]

    // ---- fp32 -> fp16 conversions (grids computed from element counts) ----
    F2H(w_ih0, 0, 2048 * 1536 / 4);
    F2H(w_hh0, 1, 2048 * 512 / 4);
    F2H(w_ih1, 2, 2048 * 1024 / 4);
    F2H(w_hh1, 3, 2048 * 512 / 4);
    F2H(w_ih2, 4, 2048 * 1024 / 4);
    F2H(w_hh2, 5, 2048 * 512 / 4);
    F2H(wc, 6, 128 * 512 / 4);
    F2H(clip, 7, (BB * LL * CD) / 4);      // 16.78M quads -> 65536 blocks (was half!)
    F2H(xt, 8, BH / 4);
    F2H(event, 9, BH / 4);
    F2H(state_h, 10, BH / 4);
    F2H(state_h + BH, 11, BH / 4);
    F2H(state_h + 2 * BH, 12, BH / 4);

    k_vbias<<<(G4H * 32) / 256, 256>>>(video, w_ih0, b_ih0, b_hh0);

    dim3 ggrid(G4H / 64, BB / 64);   // (32, 8)

    // layer 0
    k_gemm3_h<<<ggrid, 128>>>(0, b_ih0, b_hh0, /*bias_mode=*/1);
    k_lstm_act<<<BH / 256, 256>>>(state_c, nh, nc, nullptr, /*hsel=*/0);

    // layer 1
    k_gemm3_h<<<ggrid, 128>>>(1, b_ih1, b_hh1, 0);
    k_lstm_act<<<BH / 256, 256>>>(state_c + BH, nh + BH, nc + BH, nullptr, /*hsel=*/1);

    // attention
    k_atth<<<BB, 128>>>(nh + BH, wh, bh);
    k_att_h<<<(BB * LL) / 64, 256>>>(bc, wa, ba);
    k_softmax<<<BB, 256>>>(cmask);
    k_attres<<<BB, 256>>>();

    // layer 2
    k_gemm3_h<<<ggrid, 128>>>(2, b_ih2, b_hh2, 0);
    k_lstm_act<<<BH / 256, 256>>>(state_c + 2 * BH, nh + 2 * BH, nc + 2 * BH, h2o, /*hsel=*/2);
}